// round 1
// baseline (speedup 1.0000x reference)
#include <cuda_runtime.h>

// HysteresisThresholding: 2048x2048 canny-style hysteresis with gap-1 and
// gap-2 8-connectivity, single persistent kernel with hand-rolled grid
// barrier (co-residency guaranteed via occupancy API at launch).
//
// Outputs (concatenated in d_out, float32):
//   [0 .. N)    low_thresholded  = thin < 0.3 ? 0 : thin
//   [N .. 2N)   high_threshold   = thin < 0.7 ? 0 : thin
//   [2N .. 3N)  final            = active ? thin : 0
//
// Flood fill runs on bit-packed masks (1 bit/pixel, 64 u32 words per row).
// In-place (chaotic) iteration is valid: the operator is monotone, so the
// least fixed point is scheduling-independent.

#define H_IMG 2048
#define W_IMG 2048
#define WX 64                    // 32-bit words per image row
#define N_WORDS (H_IMG * WX)     // 131072
#define N_PIX (H_IMG * W_IMG)    // 4194304
#define LOW_T 0.3f
#define HIGH_T 0.7f
#define MAX_PASS 256

__device__ unsigned g_active[N_WORDS];
__device__ unsigned g_weak[N_WORDS];     // weak & tmask (pre-masked)
__device__ unsigned g_changed[MAX_PASS];
__device__ unsigned g_bar_count;
__device__ unsigned g_bar_gen;

__device__ __forceinline__ void grid_barrier(unsigned nblocks) {
    __syncthreads();
    if (threadIdx.x == 0) {
        __threadfence();
        volatile unsigned* genp = &g_bar_gen;
        unsigned gen = *genp;
        unsigned arr = atomicAdd(&g_bar_count, 1u);
        if (arr == nblocks - 1u) {
            atomicExch(&g_bar_count, 0u);
            __threadfence();
            atomicAdd(&g_bar_gen, 1u);
        } else {
            while (*genp == gen) { __nanosleep(64); }
        }
        __threadfence();
    }
    __syncthreads();
}

__device__ __forceinline__ unsigned ldA(int r, int w) {
    if ((unsigned)r >= (unsigned)H_IMG || (unsigned)w >= (unsigned)WX) return 0u;
    return __ldcg(&g_active[r * WX + w]);
}

__global__ void __launch_bounds__(256)
hyst_kernel(const float* __restrict__ thin, float* __restrict__ out, unsigned nblocks) {
    const int T = gridDim.x * blockDim.x;
    const int tid = blockIdx.x * blockDim.x + threadIdx.x;
    const unsigned lane = threadIdx.x & 31u;

    float* out_low   = out;
    float* out_high  = out + N_PIX;
    float* out_final = out + 2 * N_PIX;

    // ---------------- Phase 1: thresholds + bit-pack masks ----------------
    for (int i = tid; i < MAX_PASS; i += T) g_changed[i] = 0u;

    for (int p = tid; p < N_PIX; p += T) {
        float v = thin[p];
        out_low[p]  = (v < LOW_T)  ? 0.0f : v;
        out_high[p] = (v < HIGH_T) ? 0.0f : v;
        unsigned wk = __ballot_sync(0xFFFFFFFFu, v >= LOW_T);
        unsigned ac = __ballot_sync(0xFFFFFFFFu, v >= HIGH_T);
        if (lane == 0) {
            int idx = p >> 5;
            int r  = idx >> 6;
            int wx = idx & 63;
            unsigned tcol = (wx == 0) ? 0xFFFFFFFEu
                          : (wx == WX - 1) ? 0x3FFFFFFFu : 0xFFFFFFFFu;
            unsigned trow = (r >= 1 && r <= H_IMG - 3) ? 0xFFFFFFFFu : 0u;
            g_weak[idx]   = wk & tcol & trow;
            g_active[idx] = ac;
        }
    }

    grid_barrier(nblocks);

    // ---------------- Phase 2: flood fill to fixed point ----------------
    for (int pass = 0; pass < MAX_PASS; pass++) {
        unsigned local_changed = 0u;
        for (int idx = tid; idx < N_WORDS; idx += T) {
            unsigned w1  = g_weak[idx];
            unsigned act = __ldcg(&g_active[idx]);
            unsigned todo = w1 & ~act;
            if (!todo) continue;
            int r  = idx >> 6;
            int wx = idx & 63;

            // gap-1 neighborhood
            unsigned am1l = ldA(r - 1, wx - 1), am1c = ldA(r - 1, wx), am1r = ldA(r - 1, wx + 1);
            unsigned a0l  = ldA(r, wx - 1),                            a0r  = ldA(r, wx + 1);
            unsigned ap1l = ldA(r + 1, wx - 1), ap1c = ldA(r + 1, wx), ap1r = ldA(r + 1, wx + 1);

            unsigned conn =
                  am1c | __funnelshift_l(am1l, am1c, 1) | __funnelshift_r(am1c, am1r, 1)
                |        __funnelshift_l(a0l,  act,  1) | __funnelshift_r(act,  a0r,  1)
                | ap1c | __funnelshift_l(ap1l, ap1c, 1) | __funnelshift_r(ap1c, ap1r, 1);

            unsigned add = todo & conn;
            unsigned rem = todo & ~conn;

            unsigned c2m = (r >= 2 && r <= H_IMG - 4)
                ? ((wx == 0) ? 0xFFFFFFFCu : (wx == WX - 1) ? 0x1FFFFFFFu : 0xFFFFFFFFu)
                : 0u;

            if (rem & c2m) {
                unsigned am2l = ldA(r - 2, wx - 1), am2c = ldA(r - 2, wx), am2r = ldA(r - 2, wx + 1);
                unsigned ap2l = ldA(r + 2, wx - 1), ap2c = ldA(r + 2, wx), ap2r = ldA(r + 2, wx + 1);
                unsigned conn2 =
                      am2c | __funnelshift_l(am2l, am2c, 2) | __funnelshift_r(am2c, am2r, 2)
                    |        __funnelshift_l(a0l,  act,  2) | __funnelshift_r(act,  a0r,  2)
                    | ap2c | __funnelshift_l(ap2l, ap2c, 2) | __funnelshift_r(ap2c, ap2r, 2);
                add |= rem & c2m & conn2;
            }

            if (add) {
                __stcg(&g_active[idx], act | add);
                local_changed = 1u;
            }
        }
        if (local_changed) g_changed[pass] = 1u;
        grid_barrier(nblocks);
        if (*(volatile unsigned*)&g_changed[pass] == 0u) break;
    }

    // ---------------- Phase 3: final output ----------------
    for (int p = tid; p < N_PIX; p += T) {
        unsigned word = 0u;
        if (lane == 0) word = __ldcg(&g_active[p >> 5]);
        word = __shfl_sync(0xFFFFFFFFu, word, 0);
        float v = thin[p];
        out_final[p] = ((word >> lane) & 1u) ? v : 0.0f;
    }
}

extern "C" void kernel_launch(void* const* d_in, const int* in_sizes, int n_in,
                              void* d_out, int out_size) {
    const float* thin = (const float*)d_in[0];
    float* out = (float*)d_out;
    (void)in_sizes; (void)n_in; (void)out_size;

    int dev = 0;
    cudaGetDevice(&dev);
    int nsm = 0;
    cudaDeviceGetAttribute(&nsm, cudaDevAttrMultiProcessorCount, dev);
    if (nsm <= 0) nsm = 148;
    int maxb = 0;
    cudaOccupancyMaxActiveBlocksPerMultiprocessor(&maxb, hyst_kernel, 256, 0);
    if (maxb < 1) maxb = 1;
    unsigned grid = (unsigned)(nsm * maxb);

    hyst_kernel<<<grid, 256>>>(thin, out, grid);
}

// round 2
// speedup vs baseline: 3.3611x; 3.3611x over previous
#include <cuda_runtime.h>

// HysteresisThresholding on 2048x2048: thresholds + gap-1/gap-2 8-connected
// hysteresis flood fill. Single persistent kernel, one block per SM, each
// block owns a row band and converges it locally in shared memory; global
// passes only exchange 4-row halos. Flood operator is monotone, so chaotic
// (in-place, any order) iteration reaches the same least fixed point as the
// reference's synchronous loop.

#define H_IMG 2048
#define W_IMG 2048
#define WX 64                    // 32-bit words per image row
#define N_WORDS (H_IMG * WX)
#define N_PIX (H_IMG * W_IMG)
#define LOW_T 0.3f
#define HIGH_T 0.7f
#define MAX_PASS 256
#define MAX_ROWS 16              // max band height
#define NT 1024                  // threads per block

__device__ unsigned g_active[N_WORDS];
__device__ unsigned g_changed[MAX_PASS];
__device__ unsigned g_bar_count;
__device__ unsigned g_bar_gen;

__device__ __forceinline__ void grid_barrier(unsigned nblocks) {
    __syncthreads();
    if (threadIdx.x == 0) {
        __threadfence();
        volatile unsigned* genp = &g_bar_gen;
        unsigned gen = *genp;
        unsigned arr = atomicAdd(&g_bar_count, 1u);
        if (arr == nblocks - 1u) {
            atomicExch(&g_bar_count, 0u);
            __threadfence();
            atomicAdd(&g_bar_gen, 1u);
        } else {
            while (*genp == gen) { __nanosleep(32); }
        }
        __threadfence();
    }
    __syncthreads();
}

__global__ void __launch_bounds__(NT, 1)
hyst_kernel(const float* __restrict__ thin, float* __restrict__ out,
            int rows_per, unsigned nblocks) {
    __shared__ unsigned s_act[(MAX_ROWS + 4) * WX];  // band + 2-row halo each side
    __shared__ unsigned s_w1[MAX_ROWS * WX];         // weak & gap-1 trace mask
    __shared__ unsigned s_w2[MAX_ROWS * WX];         // weak & gap-2 mask

    const int tid  = threadIdx.x;
    const int lane = tid & 31;
    const int warp = tid >> 5;
    const int r0   = blockIdx.x * rows_per;
    const int nrows  = max(0, min(H_IMG - r0, rows_per));
    const int nwords = nrows * WX;

    float* out_low   = out;
    float* out_high  = out + N_PIX;
    float* out_final = out + 2 * N_PIX;

    // -------- init smem (zero halos) + pass flags --------
    for (int i = tid; i < (MAX_ROWS + 4) * WX; i += NT) s_act[i] = 0u;
    if (blockIdx.x == 0)
        for (int i = tid; i < MAX_PASS; i += NT) g_changed[i] = 0u;

    // -------- Phase 1: thresholds + bit-pack masks (band-local) --------
    for (int w = warp; w < nwords; w += NT / 32) {
        int gw = r0 * WX + w;
        int p  = gw * 32 + lane;
        float v = thin[p];
        out_low[p]  = (v < LOW_T)  ? 0.0f : v;
        out_high[p] = (v < HIGH_T) ? 0.0f : v;
        unsigned wk = __ballot_sync(0xFFFFFFFFu, v >= LOW_T);
        unsigned ac = __ballot_sync(0xFFFFFFFFu, v >= HIGH_T);
        if (lane == 0) {
            int r = gw >> 6, wx = gw & 63;
            unsigned t1c = (wx == 0) ? 0xFFFFFFFEu : (wx == WX - 1) ? 0x3FFFFFFFu : 0xFFFFFFFFu;
            unsigned t1r = (r >= 1 && r <= H_IMG - 3) ? 0xFFFFFFFFu : 0u;
            unsigned t2c = (wx == 0) ? 0xFFFFFFFCu : (wx == WX - 1) ? 0x1FFFFFFFu : 0xFFFFFFFFu;
            unsigned t2r = (r >= 2 && r <= H_IMG - 4) ? 0xFFFFFFFFu : 0u;
            s_w1[w] = wk & t1c & t1r;
            s_w2[w] = wk & t2c & t2r;
            s_act[((w >> 6) + 2) * WX + wx] = ac;
            __stcg(&g_active[gw], ac);
        }
    }

    grid_barrier(nblocks);

    // -------- Phase 2: flood fill, band-local convergence per pass --------
    for (int pass = 0; pass < MAX_PASS; pass++) {
        // reload 4 halo rows from global
        for (int i = tid; i < 4 * WX; i += NT) {
            int hr = i >> 6, wx = i & 63;
            int gr = (hr < 2) ? (r0 - 2 + hr) : (r0 + nrows + (hr - 2));
            int sr = (hr < 2) ? hr : (nrows + hr);
            unsigned v = 0u;
            if (gr >= 0 && gr < H_IMG) v = __ldcg(&g_active[gr * WX + wx]);
            s_act[sr * WX + wx] = v;
        }
        __syncthreads();

        bool band_changed = false;
        for (;;) {
            bool ch = false;
            if (tid < nwords) {
                int wx = tid & 63;
                int sr = (tid >> 6) + 2;
                unsigned c  = s_act[sr * WX + wx];
                unsigned w1 = s_w1[tid];
                unsigned w2 = s_w2[tid];
                unsigned todo = (w1 | w2) & ~c;
                if (todo) {
                    auto S = [&](int r_, int x_) -> unsigned {
                        return ((unsigned)x_ < (unsigned)WX) ? s_act[r_ * WX + x_] : 0u;
                    };
                    unsigned l  = S(sr, wx - 1),      rr = S(sr, wx + 1);
                    unsigned u1 = S(sr - 1, wx), u1l = S(sr - 1, wx - 1), u1r = S(sr - 1, wx + 1);
                    unsigned d1 = S(sr + 1, wx), d1l = S(sr + 1, wx - 1), d1r = S(sr + 1, wx + 1);
                    unsigned conn1 =
                          u1 | __funnelshift_l(u1l, u1, 1) | __funnelshift_r(u1, u1r, 1)
                        |      __funnelshift_l(l,   c,  1) | __funnelshift_r(c,  rr,  1)
                        | d1 | __funnelshift_l(d1l, d1, 1) | __funnelshift_r(d1, d1r, 1);
                    unsigned nw = c | (w1 & conn1);
                    if (w2 & ~nw) {
                        unsigned u2 = S(sr - 2, wx), u2l = S(sr - 2, wx - 1), u2r = S(sr - 2, wx + 1);
                        unsigned d2 = S(sr + 2, wx), d2l = S(sr + 2, wx - 1), d2r = S(sr + 2, wx + 1);
                        unsigned conn2 =
                              u2 | __funnelshift_l(u2l, u2, 2) | __funnelshift_r(u2, u2r, 2)
                            |      __funnelshift_l(l,   c,  2) | __funnelshift_r(c,  rr,  2)
                            | d2 | __funnelshift_l(d2l, d2, 2) | __funnelshift_r(d2, d2r, 2);
                        nw |= w2 & conn2;
                    }
                    // in-word horizontal closure through weak runs (gap 1 + 2)
                    #pragma unroll
                    for (int k = 0; k < 5; k++) {
                        unsigned sp = nw;
                        nw |= (w1 & ((sp << 1) | (sp >> 1)))
                            | (w2 & ((sp << 2) | (sp >> 2)));
                    }
                    if (nw != c) { s_act[sr * WX + wx] = nw; ch = true; }
                }
            }
            if (!__syncthreads_or(ch ? 1 : 0)) break;
            band_changed = true;
        }

        if (band_changed) {
            if (tid < nwords)
                __stcg(&g_active[r0 * WX + tid],
                       s_act[((tid >> 6) + 2) * WX + (tid & 63)]);
            if (tid == 0) __stcg(&g_changed[pass], 1u);
        }

        grid_barrier(nblocks);
        if (*(volatile unsigned*)&g_changed[pass] == 0u) break;
    }

    // -------- Phase 3: final output from converged smem band --------
    for (int w = warp; w < nwords; w += NT / 32) {
        int gw = r0 * WX + w;
        int p  = gw * 32 + lane;
        unsigned word = s_act[((w >> 6) + 2) * WX + (w & 63)];
        float v = thin[p];
        out_final[p] = ((word >> lane) & 1u) ? v : 0.0f;
    }
}

extern "C" void kernel_launch(void* const* d_in, const int* in_sizes, int n_in,
                              void* d_out, int out_size) {
    const float* thin = (const float*)d_in[0];
    float* out = (float*)d_out;
    (void)in_sizes; (void)n_in; (void)out_size;

    int dev = 0;
    cudaGetDevice(&dev);
    int nsm = 0;
    cudaDeviceGetAttribute(&nsm, cudaDevAttrMultiProcessorCount, dev);
    if (nsm <= 0) nsm = 148;

    int rows_per = (H_IMG + nsm - 1) / nsm;
    if (rows_per > MAX_ROWS) rows_per = MAX_ROWS;   // (never on GB300; safety)
    unsigned grid = (unsigned)((H_IMG + rows_per - 1) / rows_per);

    hyst_kernel<<<grid, NT>>>(thin, out, rows_per, grid);
}